// round 3
// baseline (speedup 1.0000x reference)
#include <cuda_runtime.h>
#include <math.h>

// Problem dims
#define BATCH 32
#define TT    1024
#define DD    512
#define HH    512
#define GG    2048          // 4*H
#define LLAY  2
#define MM    (BATCH*TT)    // 32768

// Output layout in d_out (float32): seq [B,T,H], then h [B,L,H], then c [B,L,H]
#define SEQ_ELEMS  ((size_t)MM*HH)
#define HOFF       (SEQ_ELEMS)
#define COFF       (SEQ_ELEMS + (size_t)BATCH*LLAY*HH)

// Recurrence kernel config
#define NBLK   128
#define NTHR   256
#define PADROW 516          // 512 + 4 pad floats (2064B, 16B-aligned rows)
#define WS_ELEMS (16*PADROW)
#define HS_ELEMS (32*PADROW)
#define GSM_ELEMS (BATCH*16)
#define RSMEM_BYTES ((WS_ELEMS + HS_ELEMS + GSM_ELEMS) * sizeof(float))

// Scratch (device globals — no allocations allowed)
__device__ float g_xg[(size_t)MM*GG];     // 256 MB
__device__ float g_seq0[(size_t)MM*HH];   // 64 MB
__device__ float g_hbuf[2][BATCH*HH];
__device__ unsigned g_bar_count;
__device__ unsigned g_bar_gen;

// ---------------- packed f32x2 helpers (sm_100+) ----------------
__device__ __forceinline__ unsigned long long ffma2(unsigned long long a,
                                                    unsigned long long b,
                                                    unsigned long long c)
{
    unsigned long long d;
    asm("fma.rn.f32x2 %0, %1, %2, %3;" : "=l"(d) : "l"(a), "l"(b), "l"(c));
    return d;
}
__device__ __forceinline__ unsigned long long pack2(float x, float y)
{
    unsigned long long d;
    asm("mov.b64 %0, {%1, %2};" : "=l"(d) : "f"(x), "f"(y));
    return d;
}
__device__ __forceinline__ float2 unpack2(unsigned long long v)
{
    float2 r;
    asm("mov.b64 {%0, %1}, %2;" : "=f"(r.x), "=f"(r.y) : "l"(v));
    return r;
}

// ---------------- cp.async helpers ----------------
__device__ __forceinline__ void cp_async16(void* smem_dst, const void* gsrc)
{
    unsigned s = (unsigned)__cvta_generic_to_shared(smem_dst);
    asm volatile("cp.async.cg.shared.global [%0], [%1], 16;\n"
                 :: "r"(s), "l"(gsrc) : "memory");
}
#define CP_COMMIT() asm volatile("cp.async.commit_group;\n" ::: "memory")
#define CP_WAIT1()  asm volatile("cp.async.wait_group 1;\n" ::: "memory")
#define CP_WAIT0()  asm volatile("cp.async.wait_group 0;\n" ::: "memory")

// ---------------------------------------------------------------------------
// SGEMM: C[M,N] = A[M,K] @ W[K,N] + bias1[N] + bias2[N]
// 128x128 tile, BK=8, 256 threads, 8x8 per thread, FFMA2 inner product.
// ---------------------------------------------------------------------------
__global__ void __launch_bounds__(256, 2)
sgemm_bias(const float* __restrict__ A, const float* __restrict__ W,
           const float* __restrict__ bias1, const float* __restrict__ bias2,
           float* __restrict__ C, int Kdim)
{
    __shared__ float As[8][128];
    __shared__ float Bs[8][128];

    const int tid = threadIdx.x;
    const int brow = blockIdx.y, bcol = blockIdx.x;

    const float* Ablk = A + (size_t)brow * 128 * Kdim;
    const float* Wblk = W + (size_t)bcol * 128;

    const int arow = tid >> 1;
    const int ak4  = (tid & 1) * 4;
    const int wrow = tid >> 5;
    const int wn4  = (tid & 31) * 4;

    const int ty = tid >> 4;
    const int tx = tid & 15;

    unsigned long long acc[8][4];
#pragma unroll
    for (int i = 0; i < 8; i++)
#pragma unroll
        for (int j = 0; j < 4; j++) acc[i][j] = 0ull;

    for (int k0 = 0; k0 < Kdim; k0 += 8) {
        float4 av = *(const float4*)(Ablk + (size_t)arow * Kdim + k0 + ak4);
        As[ak4 + 0][arow] = av.x;
        As[ak4 + 1][arow] = av.y;
        As[ak4 + 2][arow] = av.z;
        As[ak4 + 3][arow] = av.w;
        float4 wv = *(const float4*)(Wblk + (size_t)(k0 + wrow) * GG + wn4);
        *(float4*)(&Bs[wrow][wn4]) = wv;
        __syncthreads();

#pragma unroll
        for (int kk = 0; kk < 8; kk++) {
            float a[8];
            *(float4*)&a[0] = *(const float4*)&As[kk][ty * 8];
            *(float4*)&a[4] = *(const float4*)&As[kk][ty * 8 + 4];
            ulonglong2 b01 = *(const ulonglong2*)&Bs[kk][tx * 8];
            ulonglong2 b23 = *(const ulonglong2*)&Bs[kk][tx * 8 + 4];
            unsigned long long bd[4] = { b01.x, b01.y, b23.x, b23.y };
#pragma unroll
            for (int i = 0; i < 8; i++) {
                unsigned long long ad = pack2(a[i], a[i]);
#pragma unroll
                for (int j = 0; j < 4; j++)
                    acc[i][j] = ffma2(ad, bd[j], acc[i][j]);
            }
        }
        __syncthreads();
    }

    const int row0 = brow * 128 + ty * 8;
    const int col0 = bcol * 128 + tx * 8;
    float bs[8];
#pragma unroll
    for (int j = 0; j < 8; j++) bs[j] = bias1[col0 + j] + bias2[col0 + j];

#pragma unroll
    for (int i = 0; i < 8; i++) {
        float c[8];
#pragma unroll
        for (int j = 0; j < 4; j++) {
            float2 v = unpack2(acc[i][j]);
            c[2*j]   = v.x + bs[2*j];
            c[2*j+1] = v.y + bs[2*j+1];
        }
        *(float4*)(C + (size_t)(row0 + i) * GG + col0)     = *(float4*)&c[0];
        *(float4*)(C + (size_t)(row0 + i) * GG + col0 + 4) = *(float4*)&c[4];
    }
}

// ---------------------------------------------------------------------------
// Grid barrier (128 blocks <= 148 SMs, all resident)
// ---------------------------------------------------------------------------
__device__ __forceinline__ void grid_barrier()
{
    __syncthreads();
    if (threadIdx.x == 0) {
        __threadfence();
        volatile unsigned* vgen = &g_bar_gen;
        unsigned gen = *vgen;
        unsigned arrived = atomicAdd(&g_bar_count, 1u);
        if (arrived == gridDim.x - 1) {
            g_bar_count = 0;
            __threadfence();
            atomicAdd(&g_bar_gen, 1u);
        } else {
            while (*vgen == gen) { }
            __threadfence();
        }
    }
    __syncthreads();
}

// ---------------------------------------------------------------------------
// Persistent LSTM recurrence, one layer. Block owns 4 hidden units
// (16 gate columns). Warp = 8 cols x 4 batch-groups -> w LDS is 1 phase.
// Inner product uses fma.rn.f32x2 (2 FMAs/instr). h staged via cp.async
// in two k-halves overlapped with compute.
// ---------------------------------------------------------------------------
__global__ void __launch_bounds__(NTHR, 1)
lstm_recur(const float* __restrict__ Wh_l,
           const float* __restrict__ xg,
           float* __restrict__ seq_out,
           float* __restrict__ hc_out,
           int layer)
{
    extern __shared__ float smem[];
    float* ws  = smem;                   // [16][PADROW]
    float* hs  = ws + WS_ELEMS;          // [32][PADROW]
    float* gsm = hs + HS_ELEMS;          // [32][16]

    const int tid = threadIdx.x;
    const int blk = blockIdx.x;
    const int wid = tid >> 5, lane = tid & 31;

    // compute-phase mapping: warp covers 8 cols x 4 groups
    const int col = (lane & 7) | ((wid & 1) << 3);     // 0..15
    const int grp = (lane >> 3) | ((wid >> 1) << 2);   // 0..15
    const int b0 = grp, b1 = grp + 16;
    const int gate = col >> 2, jj = col & 3;
    const int gcol = gate * 512 + blk * 4 + jj;        // global gate column

    // update-phase mapping
    const int ub  = tid >> 2;
    const int uj  = tid & 3;
    const int ujg = blk * 4 + uj;

    // Load W slice transposed into smem: ws[c][k] = Wh_l[k*G + colmap(c)]
    for (int i = tid; i < 16 * 512; i += NTHR) {
        int c = i >> 9, k = i & 511;
        int g2 = c >> 2, j2 = c & 3;
        ws[c * PADROW + k] = Wh_l[(size_t)k * GG + g2 * 512 + blk * 4 + j2];
    }

    // Zero h buffer 0 cooperatively
    for (int i = blk * NTHR + tid; i < BATCH * HH; i += NBLK * NTHR)
        __stcg(&g_hbuf[0][i], 0.f);

    float creg = 0.f;

    grid_barrier();

    const ulonglong2* wp  = (const ulonglong2*)(ws + col * PADROW);
    const ulonglong2* h0p = (const ulonglong2*)(hs + b0 * PADROW);
    const ulonglong2* h1p = (const ulonglong2*)(hs + b1 * PADROW);

    for (int t = 0; t < TT; t++) {
        // issue xg loads early (overlap with staging)
        float acc0 = xg[((size_t)b0 * TT + t) * GG + gcol];
        float acc1 = xg[((size_t)b1 * TT + t) * GG + gcol];

        // ---- stage h(t-1) via cp.async, two k-halves ----
        const float* hsrc = &g_hbuf[t & 1][0];
#pragma unroll
        for (int i = tid; i < 2048; i += NTHR) {
            int row = i >> 6, c4 = i & 63;
            cp_async16(hs + row * PADROW + c4 * 4, hsrc + row * 512 + c4 * 4);
        }
        CP_COMMIT();
#pragma unroll
        for (int i = tid; i < 2048; i += NTHR) {
            int row = i >> 6, c4 = (i & 63) + 64;
            cp_async16(hs + row * PADROW + c4 * 4, hsrc + row * 512 + c4 * 4);
        }
        CP_COMMIT();

        unsigned long long A0 = 0ull, A1 = 0ull, A2 = 0ull, A3 = 0ull;

        CP_WAIT1();
        __syncthreads();
#pragma unroll 8
        for (int k4 = 0; k4 < 64; k4++) {
            ulonglong2 w  = wp[k4];
            ulonglong2 ha = h0p[k4];
            ulonglong2 hb = h1p[k4];
            A0 = ffma2(ha.x, w.x, A0);
            A1 = ffma2(ha.y, w.y, A1);
            A2 = ffma2(hb.x, w.x, A2);
            A3 = ffma2(hb.y, w.y, A3);
        }
        CP_WAIT0();
        __syncthreads();
#pragma unroll 8
        for (int k4 = 64; k4 < 128; k4++) {
            ulonglong2 w  = wp[k4];
            ulonglong2 ha = h0p[k4];
            ulonglong2 hb = h1p[k4];
            A0 = ffma2(ha.x, w.x, A0);
            A1 = ffma2(ha.y, w.y, A1);
            A2 = ffma2(hb.x, w.x, A2);
            A3 = ffma2(hb.y, w.y, A3);
        }

        float2 p0 = unpack2(A0), p1 = unpack2(A1);
        float2 p2 = unpack2(A2), p3 = unpack2(A3);
        acc0 += (p0.x + p0.y) + (p1.x + p1.y);
        acc1 += (p2.x + p2.y) + (p3.x + p3.y);

        gsm[b0 * 16 + col] = acc0;
        gsm[b1 * 16 + col] = acc1;
        __syncthreads();

        // ---- cell update (128 threads) ----
        if (tid < 128) {
            float f  = gsm[ub * 16 + 0  + uj];
            float g  = gsm[ub * 16 + 4  + uj];
            float ii = gsm[ub * 16 + 8  + uj];
            float o  = gsm[ub * 16 + 12 + uj];
            f  = 1.f / (1.f + expf(-f));
            ii = 1.f / (1.f + expf(-ii));
            o  = 1.f / (1.f + expf(-o));
            g  = tanhf(g);
            creg = f * creg + ii * g;
            float hval = o * tanhf(creg);

            __stcg(&g_hbuf[(t + 1) & 1][ub * HH + ujg], hval);
            seq_out[((size_t)ub * TT + t) * HH + ujg] = hval;

            if (t == TT - 1) {
                hc_out[HOFF + (size_t)(ub * LLAY + layer) * HH + ujg] = hval;
                hc_out[COFF + (size_t)(ub * LLAY + layer) * HH + ujg] = creg;
            }
        }

        grid_barrier();
    }
}

// ---------------------------------------------------------------------------
extern "C" void kernel_launch(void* const* d_in, const int* in_sizes, int n_in,
                              void* d_out, int out_size)
{
    const float* x  = (const float*)d_in[0];
    const float* Wx = (const float*)d_in[1];
    const float* bx = (const float*)d_in[2];
    const float* Wh = (const float*)d_in[3];
    const float* bh = (const float*)d_in[4];
    float* out = (float*)d_out;

    float *xg = nullptr, *seq0 = nullptr;
    cudaGetSymbolAddress((void**)&xg, g_xg);
    cudaGetSymbolAddress((void**)&seq0, g_seq0);

    cudaFuncSetAttribute(lstm_recur, cudaFuncAttributeMaxDynamicSharedMemorySize,
                         (int)RSMEM_BYTES);

    dim3 gdim(GG / 128, MM / 128);

    // Layer 0
    sgemm_bias<<<gdim, 256>>>(x, Wx, bx, bh, xg, DD);
    lstm_recur<<<NBLK, NTHR, RSMEM_BYTES>>>(Wh, xg, seq0, out, 0);

    // Layer 1
    sgemm_bias<<<gdim, 256>>>(seq0, Wx + (size_t)DD * GG, bx + GG, bh + GG, xg, HH);
    lstm_recur<<<NBLK, NTHR, RSMEM_BYTES>>>(Wh + (size_t)HH * GG, xg, out, out, 1);
}

// round 4
// speedup vs baseline: 1.1271x; 1.1271x over previous
#include <cuda_runtime.h>
#include <math.h>

// Problem dims
#define BATCH 32
#define TT    1024
#define DD    512
#define HH    512
#define GG    2048
#define LLAY  2
#define MM    (BATCH*TT)

// Output layout in d_out (float32): seq [B,T,H], then h [B,L,H], then c [B,L,H]
#define SEQ_ELEMS  ((size_t)MM*HH)
#define HOFF       (SEQ_ELEMS)
#define COFF       (SEQ_ELEMS + (size_t)BATCH*LLAY*HH)

// Recurrence config: 128 blocks = 32 unit-groups x 4 batch-groups
#define NBLK 128
#define NTHR 256
#define NBG  4      // batch groups (8 batches each)
#define NUG  32     // unit groups (16 units each)
#define BPB  8      // batches per block
#define UPB  16     // hidden units per block (x4 gates = 64 cols)
#define HROW 528    // 512 + 4-float skew per 128-k segment (bank-conflict free)

// Scratch (device globals)
__device__ float g_xg[(size_t)MM*GG];     // 256 MB
__device__ float g_seq0[(size_t)MM*HH];   // 64 MB
__device__ float g_hbuf[2][BATCH*HH];
__device__ unsigned g_flags[NBG][NUG];
__device__ unsigned g_bar_count;
__device__ unsigned g_bar_gen;

// ---------------- packed f32x2 helpers ----------------
__device__ __forceinline__ unsigned long long ffma2(unsigned long long a,
                                                    unsigned long long b,
                                                    unsigned long long c)
{
    unsigned long long d;
    asm("fma.rn.f32x2 %0, %1, %2, %3;" : "=l"(d) : "l"(a), "l"(b), "l"(c));
    return d;
}
__device__ __forceinline__ unsigned long long pack2(float x, float y)
{
    unsigned long long d;
    asm("mov.b64 %0, {%1, %2};" : "=l"(d) : "f"(x), "f"(y));
    return d;
}
__device__ __forceinline__ float2 unpack2(unsigned long long v)
{
    float2 r;
    asm("mov.b64 {%0, %1}, %2;" : "=f"(r.x), "=f"(r.y) : "l"(v));
    return r;
}

// ---------------- acquire/release + fence ----------------
__device__ __forceinline__ unsigned ld_acquire_gpu(const unsigned* p)
{
    unsigned v;
    asm volatile("ld.acquire.gpu.global.b32 %0, [%1];" : "=r"(v) : "l"(p) : "memory");
    return v;
}
__device__ __forceinline__ void st_release_gpu(unsigned* p, unsigned v)
{
    asm volatile("st.release.gpu.global.b32 [%0], %1;" :: "l"(p), "r"(v) : "memory");
}
__device__ __forceinline__ void fence_gpu()
{
    asm volatile("fence.acq_rel.gpu;" ::: "memory");
}

// ---------------- cp.async ----------------
__device__ __forceinline__ void cp_async16(void* smem_dst, const void* gsrc)
{
    unsigned s = (unsigned)__cvta_generic_to_shared(smem_dst);
    asm volatile("cp.async.cg.shared.global [%0], [%1], 16;\n"
                 :: "r"(s), "l"(gsrc) : "memory");
}
#define CP_COMMIT() asm volatile("cp.async.commit_group;\n" ::: "memory")
#define CP_WAIT0()  asm volatile("cp.async.wait_group 0;\n" ::: "memory")

// ---------------------------------------------------------------------------
// SGEMM: C[M,N] = A[M,K] @ W[K,N] + bias1[N] + bias2[N]   (unchanged, FFMA2)
// ---------------------------------------------------------------------------
__global__ void __launch_bounds__(256, 2)
sgemm_bias(const float* __restrict__ A, const float* __restrict__ W,
           const float* __restrict__ bias1, const float* __restrict__ bias2,
           float* __restrict__ C, int Kdim)
{
    __shared__ float As[8][128];
    __shared__ float Bs[8][128];

    const int tid = threadIdx.x;
    const int brow = blockIdx.y, bcol = blockIdx.x;

    const float* Ablk = A + (size_t)brow * 128 * Kdim;
    const float* Wblk = W + (size_t)bcol * 128;

    const int arow = tid >> 1;
    const int ak4  = (tid & 1) * 4;
    const int wrow = tid >> 5;
    const int wn4  = (tid & 31) * 4;
    const int ty = tid >> 4;
    const int tx = tid & 15;

    unsigned long long acc[8][4];
#pragma unroll
    for (int i = 0; i < 8; i++)
#pragma unroll
        for (int j = 0; j < 4; j++) acc[i][j] = 0ull;

    for (int k0 = 0; k0 < Kdim; k0 += 8) {
        float4 av = *(const float4*)(Ablk + (size_t)arow * Kdim + k0 + ak4);
        As[ak4 + 0][arow] = av.x;
        As[ak4 + 1][arow] = av.y;
        As[ak4 + 2][arow] = av.z;
        As[ak4 + 3][arow] = av.w;
        float4 wv = *(const float4*)(Wblk + (size_t)(k0 + wrow) * GG + wn4);
        *(float4*)(&Bs[wrow][wn4]) = wv;
        __syncthreads();

#pragma unroll
        for (int kk = 0; kk < 8; kk++) {
            float a[8];
            *(float4*)&a[0] = *(const float4*)&As[kk][ty * 8];
            *(float4*)&a[4] = *(const float4*)&As[kk][ty * 8 + 4];
            ulonglong2 b01 = *(const ulonglong2*)&Bs[kk][tx * 8];
            ulonglong2 b23 = *(const ulonglong2*)&Bs[kk][tx * 8 + 4];
            unsigned long long bd[4] = { b01.x, b01.y, b23.x, b23.y };
#pragma unroll
            for (int i = 0; i < 8; i++) {
                unsigned long long ad = pack2(a[i], a[i]);
#pragma unroll
                for (int j = 0; j < 4; j++)
                    acc[i][j] = ffma2(ad, bd[j], acc[i][j]);
            }
        }
        __syncthreads();
    }

    const int row0 = brow * 128 + ty * 8;
    const int col0 = bcol * 128 + tx * 8;
    float bs[8];
#pragma unroll
    for (int j = 0; j < 8; j++) bs[j] = bias1[col0 + j] + bias2[col0 + j];

#pragma unroll
    for (int i = 0; i < 8; i++) {
        float c[8];
#pragma unroll
        for (int j = 0; j < 4; j++) {
            float2 v = unpack2(acc[i][j]);
            c[2*j]   = v.x + bs[2*j];
            c[2*j+1] = v.y + bs[2*j+1];
        }
        *(float4*)(C + (size_t)(row0 + i) * GG + col0)     = *(float4*)&c[0];
        *(float4*)(C + (size_t)(row0 + i) * GG + col0 + 4) = *(float4*)&c[4];
    }
}

// ---------------------------------------------------------------------------
// Startup-only grid barrier (atomic; used once per recurrence launch)
// ---------------------------------------------------------------------------
__device__ __forceinline__ void grid_barrier()
{
    __syncthreads();
    if (threadIdx.x == 0) {
        __threadfence();
        volatile unsigned* vgen = &g_bar_gen;
        unsigned gen = *vgen;
        unsigned arrived = atomicAdd(&g_bar_count, 1u);
        if (arrived == gridDim.x - 1) {
            g_bar_count = 0;
            __threadfence();
            atomicAdd(&g_bar_gen, 1u);
        } else {
            while (*vgen == gen) { }
            __threadfence();
        }
    }
    __syncthreads();
}

// ---------------------------------------------------------------------------
// Persistent LSTM recurrence. Block (ug, bg): 16 units x 4 gates x 8 batches.
// Weights in registers (k-split over 4 segments), h staged via cp.async,
// per-batch-group flag sync (32 producers), no atomics in the loop.
// ---------------------------------------------------------------------------
__global__ void __launch_bounds__(NTHR, 1)
lstm_recur(const float* __restrict__ Wh_l,
           const float* __restrict__ xg,
           float* __restrict__ seq_out,
           float* __restrict__ hc_out,
           int layer)
{
    __shared__ __align__(16) float hs[BPB * HROW];  // staged h, skewed rows
    __shared__ float gsm[BPB * 64];                 // gates [batch][col]

    const int tid  = threadIdx.x;
    const int wid  = tid >> 5, lane = tid & 31;
    const int ug   = blockIdx.x & 31;
    const int bg   = blockIdx.x >> 5;

    // compute mapping: col = gate*16 + unit_local (0..63), kseg s (0..3)
    const int col  = (wid << 3) | (lane & 7);
    const int s    = lane >> 3;
    const int gate = col >> 4;
    const int ul   = col & 15;
    const int gcol = gate * 512 + ug * 16 + ul;

    // update mapping (tid < 128): batch ub (0..7), unit uj (0..15)
    const int ub = tid >> 4;
    const int uj = tid & 15;
    const int bglob = bg * 8 + ub;
    const int uglob = ug * 16 + uj;

    // ---- load my weight k-slice into registers (packed f32x2) ----
    unsigned long long w2[64];
    {
        const float* wp = Wh_l + (size_t)(s * 128) * GG + gcol;
#pragma unroll 8
        for (int kk = 0; kk < 64; kk++) {
            float a = wp[(size_t)(2 * kk) * GG];
            float b = wp[(size_t)(2 * kk + 1) * GG];
            w2[kk] = pack2(a, b);
        }
    }

    // ---- init: my flag, and group's h(-1)=0 ----
    if (tid == 0) g_flags[bg][ug] = 0;
    if (ug == 0) {
        float* hz = &g_hbuf[0][bg * 8 * 512];
        for (int i = tid; i < (8 * 512) / 4; i += NTHR)
            __stcg((float4*)hz + i, make_float4(0.f, 0.f, 0.f, 0.f));
    }

    float creg = 0.f;

    grid_barrier();   // once: all flags zeroed, h(-1) zeroed

    for (int t = 0; t < TT; t++) {
        // prefetch xg for the update phase (independent of flags)
        float xgv0 = 0.f, xgv1 = 0.f, xgv2 = 0.f, xgv3 = 0.f;
        if (tid < 128) {
            const float* xp = xg + ((size_t)bglob * TT + t) * GG + ug * 16 + uj;
            xgv0 = __ldcg(xp);
            xgv1 = __ldcg(xp + 512);
            xgv2 = __ldcg(xp + 1024);
            xgv3 = __ldcg(xp + 1536);
        }

        // ---- wait for group's h(t-1): flags >= t (trivially true at t=0) ----
        if (t > 0 && tid < 32) {
            const unsigned tok = (unsigned)t;
            const unsigned* fp = &g_flags[bg][tid];
            while (true) {
                unsigned v = ld_acquire_gpu(fp);
                if (__all_sync(0xffffffffu, v >= tok)) break;
            }
        }
        __syncthreads();

        // ---- stage h(t-1) [8 x 512] into skewed smem via cp.async ----
        {
            const float* hsrc = &g_hbuf[t & 1][bg * 8 * 512];
#pragma unroll
            for (int i = tid; i < 1024; i += NTHR) {
                int r = i >> 7, g4 = i & 127;
                cp_async16(&hs[r * HROW + (g4 >> 5) * 132 + (g4 & 31) * 4],
                           hsrc + r * 512 + g4 * 4);
            }
            CP_COMMIT();
            CP_WAIT0();
        }
        __syncthreads();

        // ---- dot products: col x my kseg x 8 batches, weights in regs ----
        unsigned long long acc[8];
#pragma unroll
        for (int b = 0; b < 8; b++) acc[b] = 0ull;

#pragma unroll
        for (int k4 = 0; k4 < 32; k4++) {
#pragma unroll
            for (int b = 0; b < 8; b++) {
                ulonglong2 h2 = *(const ulonglong2*)&hs[b * HROW + s * 132 + k4 * 4];
                acc[b] = ffma2(h2.x, w2[2 * k4], acc[b]);
                acc[b] = ffma2(h2.y, w2[2 * k4 + 1], acc[b]);
            }
        }

        // reduce across the 4 ksegs (lanes differing in bits 3,4)
        float dot[8];
#pragma unroll
        for (int b = 0; b < 8; b++) {
            float2 p = unpack2(acc[b]);
            float v = p.x + p.y;
            v += __shfl_xor_sync(0xffffffffu, v, 8);
            v += __shfl_xor_sync(0xffffffffu, v, 16);
            dot[b] = v;
        }
        if (lane < 8) {
#pragma unroll
            for (int b = 0; b < 8; b++)
                gsm[b * 64 + col] = dot[b];
        }
        __syncthreads();

        // ---- cell update (128 threads: 8 batches x 16 units) ----
        if (tid < 128) {
            float f  = gsm[ub * 64 +  0 + uj] + xgv0;
            float g  = gsm[ub * 64 + 16 + uj] + xgv1;
            float ii = gsm[ub * 64 + 32 + uj] + xgv2;
            float o  = gsm[ub * 64 + 48 + uj] + xgv3;
            f  = 1.f / (1.f + expf(-f));
            ii = 1.f / (1.f + expf(-ii));
            o  = 1.f / (1.f + expf(-o));
            g  = tanhf(g);
            creg = f * creg + ii * g;
            float hval = o * tanhf(creg);

            __stcg(&g_hbuf[(t + 1) & 1][bglob * 512 + uglob], hval);
            seq_out[((size_t)bglob * TT + t) * HH + uglob] = hval;

            if (t == TT - 1) {
                hc_out[HOFF + (size_t)(bglob * LLAY + layer) * HH + uglob] = hval;
                hc_out[COFF + (size_t)(bglob * LLAY + layer) * HH + uglob] = creg;
            }
        }
        __syncthreads();

        // ---- publish h(t): fence + release my flag = t+1 ----
        if (tid == 0) {
            fence_gpu();
            st_release_gpu(&g_flags[bg][ug], (unsigned)(t + 1));
        }
    }
}

// ---------------------------------------------------------------------------
extern "C" void kernel_launch(void* const* d_in, const int* in_sizes, int n_in,
                              void* d_out, int out_size)
{
    const float* x  = (const float*)d_in[0];
    const float* Wx = (const float*)d_in[1];
    const float* bx = (const float*)d_in[2];
    const float* Wh = (const float*)d_in[3];
    const float* bh = (const float*)d_in[4];
    float* out = (float*)d_out;

    float *xg = nullptr, *seq0 = nullptr;
    cudaGetSymbolAddress((void**)&xg, g_xg);
    cudaGetSymbolAddress((void**)&seq0, g_seq0);

    dim3 gdim(GG / 128, MM / 128);

    // Layer 0
    sgemm_bias<<<gdim, 256>>>(x, Wx, bx, bh, xg, DD);
    lstm_recur<<<NBLK, NTHR>>>(Wh, xg, seq0, out, 0);

    // Layer 1
    sgemm_bias<<<gdim, 256>>>(seq0, Wx + (size_t)DD * GG, bx + GG, bh + GG, xg, HH);
    lstm_recur<<<NBLK, NTHR>>>(Wh + (size_t)HH * GG, xg, out, out, 1);
}

// round 7
// speedup vs baseline: 1.4122x; 1.2530x over previous
#include <cuda_runtime.h>
#include <math.h>

// Problem dims
#define BATCH 32
#define TT    1024
#define DD    512
#define HH    512
#define GG    2048
#define LLAY  2
#define MM    (BATCH*TT)

// Output layout in d_out (float32): seq [B,T,H], then h [B,L,H], then c [B,L,H]
#define SEQ_ELEMS  ((size_t)MM*HH)
#define HOFF       (SEQ_ELEMS)
#define COFF       (SEQ_ELEMS + (size_t)BATCH*LLAY*HH)

// Recurrence config: 128 blocks = 32 unit-groups x 4 batch-groups
#define NBLK 128
#define NTHR 256
#define NBG  4
#define NUG  32
#define BPB  8      // batches per block
#define UPB  16     // hidden units per block (x4 gates = 64 cols)

// Scratch (device globals) — 128B-aligned: cp.async.bulk requires 16B min
__device__ __align__(128) float g_xg[(size_t)MM*GG];
__device__ __align__(128) float g_seq0[(size_t)MM*HH];
__device__ __align__(128) float g_hbuf[2][BATCH*HH];
__device__ unsigned g_flags[NBG][NUG];
__device__ unsigned g_bar_count;
__device__ unsigned g_bar_gen;

// ---------------- packed f32x2 helpers ----------------
__device__ __forceinline__ unsigned long long ffma2(unsigned long long a,
                                                    unsigned long long b,
                                                    unsigned long long c)
{
    unsigned long long d;
    asm("fma.rn.f32x2 %0, %1, %2, %3;" : "=l"(d) : "l"(a), "l"(b), "l"(c));
    return d;
}
__device__ __forceinline__ unsigned long long pack2(float x, float y)
{
    unsigned long long d;
    asm("mov.b64 %0, {%1, %2};" : "=l"(d) : "f"(x), "f"(y));
    return d;
}
__device__ __forceinline__ float2 unpack2(unsigned long long v)
{
    float2 r;
    asm("mov.b64 {%0, %1}, %2;" : "=f"(r.x), "=f"(r.y) : "l"(v));
    return r;
}

// ---------------- acquire/release + fence ----------------
__device__ __forceinline__ unsigned ld_acquire_gpu(const unsigned* p)
{
    unsigned v;
    asm volatile("ld.acquire.gpu.global.b32 %0, [%1];" : "=r"(v) : "l"(p) : "memory");
    return v;
}
__device__ __forceinline__ void st_release_gpu(unsigned* p, unsigned v)
{
    asm volatile("st.release.gpu.global.b32 [%0], %1;" :: "l"(p), "r"(v) : "memory");
}
__device__ __forceinline__ void fence_gpu()
{
    asm volatile("fence.acq_rel.gpu;" ::: "memory");
}

// ---------------- mbarrier + bulk copy ----------------
__device__ __forceinline__ void mbar_init(unsigned mbar, unsigned count)
{
    asm volatile("mbarrier.init.shared.b64 [%0], %1;" :: "r"(mbar), "r"(count) : "memory");
}
__device__ __forceinline__ void mbar_expect_tx(unsigned mbar, unsigned bytes)
{
    asm volatile("mbarrier.arrive.expect_tx.shared.b64 _, [%0], %1;"
                 :: "r"(mbar), "r"(bytes) : "memory");
}
__device__ __forceinline__ void mbar_wait_parity(unsigned mbar, unsigned ph)
{
    asm volatile(
        "{\n\t"
        ".reg .pred P1;\n\t"
        "WAIT_LOOP_%=:\n\t"
        "mbarrier.try_wait.parity.acquire.cta.shared::cta.b64 P1, [%0], %1, 0x989680;\n\t"
        "@P1 bra.uni WAIT_DONE_%=;\n\t"
        "bra.uni WAIT_LOOP_%=;\n\t"
        "WAIT_DONE_%=:\n\t"
        "}"
        :: "r"(mbar), "r"(ph) : "memory");
}
__device__ __forceinline__ void bulk_g2s(unsigned smem_dst, const void* gsrc,
                                         unsigned bytes, unsigned mbar)
{
    asm volatile(
        "cp.async.bulk.shared::cluster.global.mbarrier::complete_tx::bytes "
        "[%0], [%1], %2, [%3];"
        :: "r"(smem_dst), "l"(gsrc), "r"(bytes), "r"(mbar) : "memory");
}

// ---------------------------------------------------------------------------
// SGEMM: C = A @ W + bias1 + bias2, 128x128 tile, FFMA2.
// ---------------------------------------------------------------------------
__global__ void __launch_bounds__(256, 2)
sgemm_bias(const float* __restrict__ A, const float* __restrict__ W,
           const float* __restrict__ bias1, const float* __restrict__ bias2,
           float* __restrict__ C, int Kdim)
{
    __shared__ float As[8][128];
    __shared__ float Bs[8][128];

    const int tid = threadIdx.x;
    const int brow = blockIdx.y, bcol = blockIdx.x;

    const float* Ablk = A + (size_t)brow * 128 * Kdim;
    const float* Wblk = W + (size_t)bcol * 128;

    const int arow = tid >> 1;
    const int ak4  = (tid & 1) * 4;
    const int wrow = tid >> 5;
    const int wn4  = (tid & 31) * 4;
    const int ty = tid >> 4;
    const int tx = tid & 15;

    unsigned long long acc[8][4];
#pragma unroll
    for (int i = 0; i < 8; i++)
#pragma unroll
        for (int j = 0; j < 4; j++) acc[i][j] = 0ull;

    for (int k0 = 0; k0 < Kdim; k0 += 8) {
        float4 av = *(const float4*)(Ablk + (size_t)arow * Kdim + k0 + ak4);
        As[ak4 + 0][arow] = av.x;
        As[ak4 + 1][arow] = av.y;
        As[ak4 + 2][arow] = av.z;
        As[ak4 + 3][arow] = av.w;
        float4 wv = *(const float4*)(Wblk + (size_t)(k0 + wrow) * GG + wn4);
        *(float4*)(&Bs[wrow][wn4]) = wv;
        __syncthreads();

#pragma unroll
        for (int kk = 0; kk < 8; kk++) {
            float a[8];
            *(float4*)&a[0] = *(const float4*)&As[kk][ty * 8];
            *(float4*)&a[4] = *(const float4*)&As[kk][ty * 8 + 4];
            ulonglong2 b01 = *(const ulonglong2*)&Bs[kk][tx * 8];
            ulonglong2 b23 = *(const ulonglong2*)&Bs[kk][tx * 8 + 4];
            unsigned long long bd[4] = { b01.x, b01.y, b23.x, b23.y };
#pragma unroll
            for (int i = 0; i < 8; i++) {
                unsigned long long ad = pack2(a[i], a[i]);
#pragma unroll
                for (int j = 0; j < 4; j++)
                    acc[i][j] = ffma2(ad, bd[j], acc[i][j]);
            }
        }
        __syncthreads();
    }

    const int row0 = brow * 128 + ty * 8;
    const int col0 = bcol * 128 + tx * 8;
    float bs[8];
#pragma unroll
    for (int j = 0; j < 8; j++) bs[j] = bias1[col0 + j] + bias2[col0 + j];

#pragma unroll
    for (int i = 0; i < 8; i++) {
        float c[8];
#pragma unroll
        for (int j = 0; j < 4; j++) {
            float2 v = unpack2(acc[i][j]);
            c[2*j]   = v.x + bs[2*j];
            c[2*j+1] = v.y + bs[2*j+1];
        }
        *(float4*)(C + (size_t)(row0 + i) * GG + col0)     = *(float4*)&c[0];
        *(float4*)(C + (size_t)(row0 + i) * GG + col0 + 4) = *(float4*)&c[4];
    }
}

// ---------------------------------------------------------------------------
// Startup-only grid barrier
// ---------------------------------------------------------------------------
__device__ __forceinline__ void grid_barrier()
{
    __syncthreads();
    if (threadIdx.x == 0) {
        __threadfence();
        volatile unsigned* vgen = &g_bar_gen;
        unsigned gen = *vgen;
        unsigned arrived = atomicAdd(&g_bar_count, 1u);
        if (arrived == gridDim.x - 1) {
            g_bar_count = 0;
            __threadfence();
            atomicAdd(&g_bar_gen, 1u);
        } else {
            while (*vgen == gen) { }
            __threadfence();
        }
    }
    __syncthreads();
}

// ---------------------------------------------------------------------------
// Persistent LSTM recurrence. Block (ug, bg): 16 units x 4 gates x 8 batches.
// h(t-1) slice (16 KB contiguous) fetched with ONE cp.async.bulk + mbarrier.
// Weights in registers, k-interleaved so LDS is conflict-free without skew.
// seq/final writes AFTER the flag release (off the critical path).
// ---------------------------------------------------------------------------
__global__ void __launch_bounds__(NTHR, 1)
lstm_recur(const float* __restrict__ Wh_l,
           const float* __restrict__ xg,
           float* __restrict__ seq_out,
           float* __restrict__ hc_out,
           int layer)
{
    __shared__ __align__(128) float hs[BPB * 512];   // 16 KB staged h
    __shared__ float gsm[BPB * 64];
    __shared__ __align__(8) unsigned long long mbar_store;

    const int tid  = threadIdx.x;
    const int wid  = tid >> 5, lane = tid & 31;
    const int ug   = blockIdx.x & 31;
    const int bg   = blockIdx.x >> 5;

    const unsigned mbar = (unsigned)__cvta_generic_to_shared(&mbar_store);
    const unsigned hs_s = (unsigned)__cvta_generic_to_shared(hs);

    // compute mapping: col 0..63, k-phase s 0..3 (k-interleaved by 16-float chunk)
    const int col  = (wid << 3) | (lane & 7);
    const int s    = lane >> 3;
    const int gate = col >> 4;
    const int ul   = col & 15;
    const int gcol = gate * 512 + ug * 16 + ul;

    // update mapping (tid < 128)
    const int ub = tid >> 4;
    const int uj = tid & 15;
    const int bglob = bg * 8 + ub;
    const int uglob = ug * 16 + uj;

    // ---- weights into registers: thread handles k = k4*16 + s*4 + {0..3} ----
    unsigned long long w2[64];
    {
#pragma unroll 8
        for (int k4 = 0; k4 < 32; k4++) {
            int kbase = k4 * 16 + s * 4;
            const float* wp = Wh_l + (size_t)kbase * GG + gcol;
            w2[2 * k4]     = pack2(wp[0],        wp[(size_t)GG]);
            w2[2 * k4 + 1] = pack2(wp[2 * GG],   wp[(size_t)3 * GG]);
        }
    }

    // ---- init: mbarrier, flag, h(-1)=0 ----
    if (tid == 0) {
        mbar_init(mbar, 1);
        g_flags[bg][ug] = 0;
    }
    if (ug == 0) {
        float* hz = &g_hbuf[0][bg * 8 * 512];
        for (int i = tid; i < (8 * 512) / 4; i += NTHR)
            __stcg((float4*)hz + i, make_float4(0.f, 0.f, 0.f, 0.f));
    }
    __syncthreads();

    float creg = 0.f;

    grid_barrier();

    for (int t = 0; t < TT; t++) {
        // prefetch xg (long-latency, independent)
        float xgv0 = 0.f, xgv1 = 0.f, xgv2 = 0.f, xgv3 = 0.f;
        if (tid < 128) {
            const float* xp = xg + ((size_t)bglob * TT + t) * GG + ug * 16 + uj;
            xgv0 = __ldcg(xp);
            xgv1 = __ldcg(xp + 512);
            xgv2 = __ldcg(xp + 1024);
            xgv3 = __ldcg(xp + 1536);
        }

        // ---- warp 0: wait group flags >= t, then ONE bulk copy of h slice ----
        if (wid == 0) {
            if (t > 0) {
                const unsigned tok = (unsigned)t;
                const unsigned* fp = &g_flags[bg][lane];
                while (true) {
                    unsigned v = ld_acquire_gpu(fp);
                    if (__all_sync(0xffffffffu, v >= tok)) break;
                }
            }
            if (lane == 0) {
                mbar_expect_tx(mbar, BPB * 512 * 4);
                bulk_g2s(hs_s, &g_hbuf[t & 1][bg * 8 * 512], BPB * 512 * 4, mbar);
            }
        }
        mbar_wait_parity(mbar, (unsigned)(t & 1));

        // ---- dot products: 64 cols x 4 k-phases x 8 batches ----
        unsigned long long acc[8];
#pragma unroll
        for (int b = 0; b < 8; b++) acc[b] = 0ull;

#pragma unroll
        for (int k4 = 0; k4 < 32; k4++) {
#pragma unroll
            for (int b = 0; b < 8; b++) {
                ulonglong2 h2 = *(const ulonglong2*)&hs[b * 512 + k4 * 16 + s * 4];
                acc[b] = ffma2(h2.x, w2[2 * k4], acc[b]);
                acc[b] = ffma2(h2.y, w2[2 * k4 + 1], acc[b]);
            }
        }

        // reduce across 4 k-phases (lane bits 3,4)
        float dot[8];
#pragma unroll
        for (int b = 0; b < 8; b++) {
            float2 p = unpack2(acc[b]);
            float v = p.x + p.y;
            v += __shfl_xor_sync(0xffffffffu, v, 8);
            v += __shfl_xor_sync(0xffffffffu, v, 16);
            dot[b] = v;
        }
        if (lane < 8) {
#pragma unroll
            for (int b = 0; b < 8; b++)
                gsm[b * 64 + col] = dot[b];
        }
        __syncthreads();

        // ---- cell update (128 threads) ----
        float hval = 0.f;
        if (tid < 128) {
            float f  = gsm[ub * 64 +  0 + uj] + xgv0;
            float g  = gsm[ub * 64 + 16 + uj] + xgv1;
            float ii = gsm[ub * 64 + 32 + uj] + xgv2;
            float o  = gsm[ub * 64 + 48 + uj] + xgv3;
            f  = 1.f / (1.f + expf(-f));
            ii = 1.f / (1.f + expf(-ii));
            o  = 1.f / (1.f + expf(-o));
            g  = tanhf(g);
            creg = f * creg + ii * g;
            hval = o * tanhf(creg);
            __stcg(&g_hbuf[(t + 1) & 1][bglob * 512 + uglob], hval);
        }
        __syncthreads();

        // ---- publish, then lazy outputs (off critical path) ----
        if (tid == 0) {
            fence_gpu();
            st_release_gpu(&g_flags[bg][ug], (unsigned)(t + 1));
        }
        if (tid < 128) {
            seq_out[((size_t)bglob * TT + t) * HH + uglob] = hval;
            if (t == TT - 1) {
                hc_out[HOFF + (size_t)(bglob * LLAY + layer) * HH + uglob] = hval;
                hc_out[COFF + (size_t)(bglob * LLAY + layer) * HH + uglob] = creg;
            }
        }
    }
}

// ---------------------------------------------------------------------------
extern "C" void kernel_launch(void* const* d_in, const int* in_sizes, int n_in,
                              void* d_out, int out_size)
{
    const float* x  = (const float*)d_in[0];
    const float* Wx = (const float*)d_in[1];
    const float* bx = (const float*)d_in[2];
    const float* Wh = (const float*)d_in[3];
    const float* bh = (const float*)d_in[4];
    float* out = (float*)d_out;

    float *xg = nullptr, *seq0 = nullptr;
    cudaGetSymbolAddress((void**)&xg, g_xg);
    cudaGetSymbolAddress((void**)&seq0, g_seq0);

    dim3 gdim(GG / 128, MM / 128);

    // Layer 0
    sgemm_bias<<<gdim, 256>>>(x, Wx, bx, bh, xg, DD);
    lstm_recur<<<NBLK, NTHR>>>(Wh, xg, seq0, out, 0);

    // Layer 1
    sgemm_bias<<<gdim, 256>>>(seq0, Wx + (size_t)DD * GG, bx + GG, bh + GG, xg, HH);
    lstm_recur<<<NBLK, NTHR>>>(Wh + (size_t)HH * GG, xg, out, out, 1);
}

// round 8
// speedup vs baseline: 1.6539x; 1.1712x over previous
#include <cuda_runtime.h>
#include <math.h>

// Problem dims
#define BATCH 32
#define TT    1024
#define DD    512
#define HH    512
#define GG    2048
#define LLAY  2
#define MM    (BATCH*TT)

// Output layout in d_out (float32): seq [B,T,H], then h [B,L,H], then c [B,L,H]
#define SEQ_ELEMS  ((size_t)MM*HH)
#define HOFF       (SEQ_ELEMS)
#define COFF       (SEQ_ELEMS + (size_t)BATCH*LLAY*HH)

// Recurrence config: 128 blocks = 32 unit-groups x 4 batch-groups
#define NBLK 128
#define NTHR 256
#define NBG  4
#define NUG  32
#define BPB  8      // batches per block

// Scratch (device globals) — 128B-aligned for cp.async.bulk
__device__ __align__(128) float g_xg[(size_t)MM*GG];
__device__ __align__(128) float g_seq0[(size_t)MM*HH];
__device__ __align__(128) float g_hbuf[2][BATCH*HH];
__device__ unsigned g_flags[NBG][NUG];
__device__ unsigned g_bar_count;
__device__ unsigned g_bar_gen;

// ---------------- packed f32x2 helpers ----------------
__device__ __forceinline__ unsigned long long ffma2(unsigned long long a,
                                                    unsigned long long b,
                                                    unsigned long long c)
{
    unsigned long long d;
    asm("fma.rn.f32x2 %0, %1, %2, %3;" : "=l"(d) : "l"(a), "l"(b), "l"(c));
    return d;
}
__device__ __forceinline__ unsigned long long pack2(float x, float y)
{
    unsigned long long d;
    asm("mov.b64 %0, {%1, %2};" : "=l"(d) : "f"(x), "f"(y));
    return d;
}
__device__ __forceinline__ float2 unpack2(unsigned long long v)
{
    float2 r;
    asm("mov.b64 {%0, %1}, %2;" : "=f"(r.x), "=f"(r.y) : "l"(v));
    return r;
}

// ---------------- fast activations (MUFU-based) ----------------
__device__ __forceinline__ float fsigmoid(float x)
{
    return __fdividef(1.f, 1.f + __expf(-x));
}
__device__ __forceinline__ float ftanh(float x)
{
    return 1.f - __fdividef(2.f, __expf(2.f * x) + 1.f);
}

// ---------------- acquire/release ----------------
__device__ __forceinline__ unsigned ld_acquire_gpu(const unsigned* p)
{
    unsigned v;
    asm volatile("ld.acquire.gpu.global.b32 %0, [%1];" : "=r"(v) : "l"(p) : "memory");
    return v;
}
__device__ __forceinline__ void st_release_gpu(unsigned* p, unsigned v)
{
    asm volatile("st.release.gpu.global.b32 [%0], %1;" :: "l"(p), "r"(v) : "memory");
}

// ---------------- mbarrier + bulk copy ----------------
__device__ __forceinline__ void mbar_init(unsigned mbar, unsigned count)
{
    asm volatile("mbarrier.init.shared.b64 [%0], %1;" :: "r"(mbar), "r"(count) : "memory");
}
__device__ __forceinline__ void mbar_expect_tx(unsigned mbar, unsigned bytes)
{
    asm volatile("mbarrier.arrive.expect_tx.shared.b64 _, [%0], %1;"
                 :: "r"(mbar), "r"(bytes) : "memory");
}
__device__ __forceinline__ void mbar_wait_parity(unsigned mbar, unsigned ph)
{
    asm volatile(
        "{\n\t"
        ".reg .pred P1;\n\t"
        "WAIT_LOOP_%=:\n\t"
        "mbarrier.try_wait.parity.acquire.cta.shared::cta.b64 P1, [%0], %1, 0x989680;\n\t"
        "@P1 bra.uni WAIT_DONE_%=;\n\t"
        "bra.uni WAIT_LOOP_%=;\n\t"
        "WAIT_DONE_%=:\n\t"
        "}"
        :: "r"(mbar), "r"(ph) : "memory");
}
__device__ __forceinline__ void bulk_g2s(unsigned smem_dst, const void* gsrc,
                                         unsigned bytes, unsigned mbar)
{
    asm volatile(
        "cp.async.bulk.shared::cluster.global.mbarrier::complete_tx::bytes "
        "[%0], [%1], %2, [%3];"
        :: "r"(smem_dst), "l"(gsrc), "r"(bytes), "r"(mbar) : "memory");
}

// ---------------------------------------------------------------------------
// SGEMM: C = A @ W + bias1 + bias2. 128x128 tile, BK=8, FFMA2,
// register double-buffer + 2x smem buffers: one __syncthreads per tile.
// ---------------------------------------------------------------------------
__global__ void __launch_bounds__(256, 2)
sgemm_bias(const float* __restrict__ A, const float* __restrict__ W,
           const float* __restrict__ bias1, const float* __restrict__ bias2,
           float* __restrict__ C, int Kdim)
{
    __shared__ __align__(16) float As[2][8][128];
    __shared__ __align__(16) float Bs[2][8][128];

    const int tid = threadIdx.x;
    const int brow = blockIdx.y, bcol = blockIdx.x;

    const float* Ablk = A + (size_t)brow * 128 * Kdim;
    const float* Wblk = W + (size_t)bcol * 128;

    const int arow = tid >> 1;
    const int ak4  = (tid & 1) * 4;
    const int wrow = tid >> 5;
    const int wn4  = (tid & 31) * 4;
    const int ty = tid >> 4;
    const int tx = tid & 15;

    const int KT = Kdim >> 3;

    unsigned long long acc[8][4];
#pragma unroll
    for (int i = 0; i < 8; i++)
#pragma unroll
        for (int j = 0; j < 4; j++) acc[i][j] = 0ull;

    // prolog: tile 0 -> smem buf 0, tile 1 -> regs
    float4 av = *(const float4*)(Ablk + (size_t)arow * Kdim + ak4);
    float4 wv = *(const float4*)(Wblk + (size_t)wrow * GG + wn4);
    As[0][ak4 + 0][arow] = av.x;
    As[0][ak4 + 1][arow] = av.y;
    As[0][ak4 + 2][arow] = av.z;
    As[0][ak4 + 3][arow] = av.w;
    *(float4*)(&Bs[0][wrow][wn4]) = wv;
    if (KT > 1) {
        av = *(const float4*)(Ablk + (size_t)arow * Kdim + 8 + ak4);
        wv = *(const float4*)(Wblk + (size_t)(8 + wrow) * GG + wn4);
    }
    __syncthreads();

    for (int kt = 0; kt < KT; kt++) {
        const int cur = kt & 1;

#pragma unroll
        for (int kk = 0; kk < 8; kk++) {
            float a[8];
            *(float4*)&a[0] = *(const float4*)&As[cur][kk][ty * 8];
            *(float4*)&a[4] = *(const float4*)&As[cur][kk][ty * 8 + 4];
            ulonglong2 b01 = *(const ulonglong2*)&Bs[cur][kk][tx * 8];
            ulonglong2 b23 = *(const ulonglong2*)&Bs[cur][kk][tx * 8 + 4];
            unsigned long long bd[4] = { b01.x, b01.y, b23.x, b23.y };
#pragma unroll
            for (int i = 0; i < 8; i++) {
                unsigned long long ad = pack2(a[i], a[i]);
#pragma unroll
                for (int j = 0; j < 4; j++)
                    acc[i][j] = ffma2(ad, bd[j], acc[i][j]);
            }
        }

        if (kt + 1 < KT) {
            const int nxt = (kt + 1) & 1;
            As[nxt][ak4 + 0][arow] = av.x;
            As[nxt][ak4 + 1][arow] = av.y;
            As[nxt][ak4 + 2][arow] = av.z;
            As[nxt][ak4 + 3][arow] = av.w;
            *(float4*)(&Bs[nxt][wrow][wn4]) = wv;
            if (kt + 2 < KT) {
                const int k0 = (kt + 2) * 8;
                av = *(const float4*)(Ablk + (size_t)arow * Kdim + k0 + ak4);
                wv = *(const float4*)(Wblk + (size_t)(k0 + wrow) * GG + wn4);
            }
            __syncthreads();
        }
    }

    const int row0 = brow * 128 + ty * 8;
    const int col0 = bcol * 128 + tx * 8;
    float bs[8];
#pragma unroll
    for (int j = 0; j < 8; j++) bs[j] = bias1[col0 + j] + bias2[col0 + j];

#pragma unroll
    for (int i = 0; i < 8; i++) {
        float c[8];
#pragma unroll
        for (int j = 0; j < 4; j++) {
            float2 v = unpack2(acc[i][j]);
            c[2*j]   = v.x + bs[2*j];
            c[2*j+1] = v.y + bs[2*j+1];
        }
        *(float4*)(C + (size_t)(row0 + i) * GG + col0)     = *(float4*)&c[0];
        *(float4*)(C + (size_t)(row0 + i) * GG + col0 + 4) = *(float4*)&c[4];
    }
}

// ---------------------------------------------------------------------------
// Startup-only grid barrier
// ---------------------------------------------------------------------------
__device__ __forceinline__ void grid_barrier()
{
    __syncthreads();
    if (threadIdx.x == 0) {
        __threadfence();
        volatile unsigned* vgen = &g_bar_gen;
        unsigned gen = *vgen;
        unsigned arrived = atomicAdd(&g_bar_count, 1u);
        if (arrived == gridDim.x - 1) {
            g_bar_count = 0;
            __threadfence();
            atomicAdd(&g_bar_gen, 1u);
        } else {
            while (*vgen == gen) { }
            __threadfence();
        }
    }
    __syncthreads();
}

// ---------------------------------------------------------------------------
// Persistent LSTM recurrence. Block (ug, bg): 16 units x 4 gates x 8 batches.
// Warp owns 2 units x 4 gates x 4 k-phases. After the k-phase shuffle
// reduction, a 32-shfl transpose gives each of 16 lanes one (unit,batch)
// cell update — no gate smem, no separate update phase, fast activations.
// Publish via st.release (no fence). h fetched with one cp.async.bulk.
// ---------------------------------------------------------------------------
__global__ void __launch_bounds__(NTHR, 1)
lstm_recur(const float* __restrict__ Wh_l,
           const float* __restrict__ xg,
           float* __restrict__ seq_out,
           float* __restrict__ hc_out,
           int layer)
{
    __shared__ __align__(128) float hs[BPB * 512];   // 16 KB staged h
    __shared__ __align__(8) unsigned long long mbar_store;

    const int tid  = threadIdx.x;
    const int wid  = tid >> 5, lane = tid & 31;
    const int ug   = blockIdx.x & 31;
    const int bg   = blockIdx.x >> 5;

    const unsigned mbar = (unsigned)__cvta_generic_to_shared(&mbar_store);
    const unsigned hs_s = (unsigned)__cvta_generic_to_shared(hs);

    // compute mapping: warp = 2 units x 4 gates x 4 k-phases
    const int u2   = lane & 1;              // unit bit
    const int gate = (lane >> 1) & 3;       // 0..3  (f,g,i,o)
    const int s    = lane >> 3;             // k-phase 0..3
    const int ul   = (wid << 1) | u2;       // unit local 0..15
    const int gcol = gate * 512 + ug * 16 + ul;

    // update mapping (lanes 0..15): unit = wid*2 + (lane&1), batch = lane>>1
    const int uu   = (wid << 1) | (lane & 1);
    const int ubat = lane >> 1;
    const int bglob = bg * 8 + ubat;
    const int uglob = ug * 16 + uu;

    // ---- weights into registers: k = k4*16 + s*4 + {0..3} ----
    unsigned long long w2[64];
    {
#pragma unroll 8
        for (int k4 = 0; k4 < 32; k4++) {
            int kbase = k4 * 16 + s * 4;
            const float* wp = Wh_l + (size_t)kbase * GG + gcol;
            w2[2 * k4]     = pack2(wp[0],      wp[(size_t)GG]);
            w2[2 * k4 + 1] = pack2(wp[2 * GG], wp[(size_t)3 * GG]);
        }
    }

    // ---- init ----
    if (tid == 0) {
        mbar_init(mbar, 1);
        g_flags[bg][ug] = 0;
    }
    if (ug == 0) {
        float* hz = &g_hbuf[0][bg * 8 * 512];
        for (int i = tid; i < (8 * 512) / 4; i += NTHR)
            __stcg((float4*)hz + i, make_float4(0.f, 0.f, 0.f, 0.f));
    }
    __syncthreads();

    float creg = 0.f;

    grid_barrier();

    for (int t = 0; t < TT; t++) {
        // prefetch xg for my cell (4 gates), lanes 0..15
        float xgv[4] = {0.f, 0.f, 0.f, 0.f};
        if (lane < 16) {
            const float* xp = xg + ((size_t)bglob * TT + t) * GG + uglob;
            xgv[0] = __ldcg(xp);
            xgv[1] = __ldcg(xp + 512);
            xgv[2] = __ldcg(xp + 1024);
            xgv[3] = __ldcg(xp + 1536);
        }

        // ---- warp 0: wait group flags >= t, then one bulk copy ----
        if (wid == 0) {
            if (t > 0) {
                const unsigned tok = (unsigned)t;
                const unsigned* fp = &g_flags[bg][lane];
                while (true) {
                    unsigned v = ld_acquire_gpu(fp);
                    if (__all_sync(0xffffffffu, v >= tok)) break;
                }
            }
            if (lane == 0) {
                mbar_expect_tx(mbar, BPB * 512 * 4);
                bulk_g2s(hs_s, &g_hbuf[t & 1][bg * 8 * 512], BPB * 512 * 4, mbar);
            }
        }
        mbar_wait_parity(mbar, (unsigned)(t & 1));

        // ---- dot products: my (col, k-phase) x 8 batches ----
        unsigned long long acc[8];
#pragma unroll
        for (int b = 0; b < 8; b++) acc[b] = 0ull;

#pragma unroll
        for (int k4 = 0; k4 < 32; k4++) {
#pragma unroll
            for (int b = 0; b < 8; b++) {
                ulonglong2 h2 = *(const ulonglong2*)&hs[b * 512 + k4 * 16 + s * 4];
                acc[b] = ffma2(h2.x, w2[2 * k4], acc[b]);
                acc[b] = ffma2(h2.y, w2[2 * k4 + 1], acc[b]);
            }
        }

        // reduce across 4 k-phases (lane bits 3,4): all lanes end with full dot
        float dot[8];
#pragma unroll
        for (int b = 0; b < 8; b++) {
            float2 p = unpack2(acc[b]);
            float v = p.x + p.y;
            v += __shfl_xor_sync(0xffffffffu, v, 8);
            v += __shfl_xor_sync(0xffffffffu, v, 16);
            dot[b] = v;
        }

        // transpose: lane L<16 gathers the 4 gate dots of (unit L&1, batch L>>1)
        float gv[4];
#pragma unroll
        for (int g = 0; g < 4; g++) {
            float got = 0.f;
#pragma unroll
            for (int b = 0; b < 8; b++) {
                float tv = __shfl_sync(0xffffffffu, dot[b], 2 * g + (lane & 1));
                if ((lane >> 1) == b) got = tv;
            }
            gv[g] = got;
        }

        // ---- cell update on lanes 0..15 of every warp ----
        float hval = 0.f;
        if (lane < 16) {
            float f  = fsigmoid(gv[0] + xgv[0]);
            float g  = ftanh   (gv[1] + xgv[1]);
            float ii = fsigmoid(gv[2] + xgv[2]);
            float o  = fsigmoid(gv[3] + xgv[3]);
            creg = f * creg + ii * g;
            hval = o * ftanh(creg);
            __stcg(&g_hbuf[(t + 1) & 1][bglob * 512 + uglob], hval);
        }
        __syncthreads();

        // ---- publish (release orders the h stores), then lazy outputs ----
        if (tid == 0)
            st_release_gpu(&g_flags[bg][ug], (unsigned)(t + 1));

        if (lane < 16) {
            seq_out[((size_t)bglob * TT + t) * HH + uglob] = hval;
            if (t == TT - 1) {
                hc_out[HOFF + (size_t)(bglob * LLAY + layer) * HH + uglob] = hval;
                hc_out[COFF + (size_t)(bglob * LLAY + layer) * HH + uglob] = creg;
            }
        }
    }
}

// ---------------------------------------------------------------------------
extern "C" void kernel_launch(void* const* d_in, const int* in_sizes, int n_in,
                              void* d_out, int out_size)
{
    const float* x  = (const float*)d_in[0];
    const float* Wx = (const float*)d_in[1];
    const float* bx = (const float*)d_in[2];
    const float* Wh = (const float*)d_in[3];
    const float* bh = (const float*)d_in[4];
    float* out = (float*)d_out;

    float *xg = nullptr, *seq0 = nullptr;
    cudaGetSymbolAddress((void**)&xg, g_xg);
    cudaGetSymbolAddress((void**)&seq0, g_seq0);

    dim3 gdim(GG / 128, MM / 128);

    // Layer 0
    sgemm_bias<<<gdim, 256>>>(x, Wx, bx, bh, xg, DD);
    lstm_recur<<<NBLK, NTHR>>>(Wh, xg, seq0, out, 0);

    // Layer 1
    sgemm_bias<<<gdim, 256>>>(seq0, Wx + (size_t)DD * GG, bx + GG, bh + GG, xg, HH);
    lstm_recur<<<NBLK, NTHR>>>(Wh + (size_t)HH * GG, xg, out, out, 1);
}